// round 13
// baseline (speedup 1.0000x reference)
#include <cuda_runtime.h>
#include <cuda_fp16.h>
#include <cstdint>

#define N_NODES 50000
#define N_EDGES 800000
#define D 128
#define N_LAYERS 3
#define N_GRAPHS 512
#define NROWS 50048                     // padded to 391*128 (device globals zero-init)
#define ND (N_NODES * D)
#define NDP (NROWS * D)

#define SCAN_BLK 512
#define SCAN_NBLK ((N_NODES + SCAN_BLK - 1) / SCAN_BLK)   // 98

// fp16 fragments: 8 ksteps x 16 nt x 32 lanes x 8 halves (bh0,bh1,bl0,bl1 as half2s)
#define KSTEPS (D / 16)                       // 8
#define FRAGH_PER_LAYER (KSTEPS * 16 * 32 * 8)   // 32768 halves = 64KB

// ---------------- scratch (device globals; no allocation allowed) ----------------
__device__ float  g_h[NDP];                 // post-GEMM features (fp32), padded
__device__ __half g_xh[NDP];                // layer input, fp16 hi, padded
__device__ __half g_xl[NDP];                // layer input, fp16 lo (residual), padded
__device__ float  g_x[ND];                  // final layer output (pool input)
__device__ __half g_wfh[N_LAYERS * FRAGH_PER_LAYER];  // W split-fp16 fragments
__device__ float  g_dis[N_NODES];
__device__ int    g_deg[N_NODES];
__device__ int    g_cur[N_NODES];
__device__ int    g_off[N_NODES + 1];
__device__ int    g_bsum[SCAN_NBLK];
__device__ float2 g_em[N_EDGES];            // (src as int bits, norm)
__device__ float  g_gsum[N_GRAPHS];
__device__ int    g_gcnt[N_GRAPHS];

#define MMA_F16(c, a0, a1, a2, a3, b0, b1) \
    asm volatile("mma.sync.aligned.m16n8k16.row.col.f32.f16.f16.f32 " \
        "{%0,%1,%2,%3}, {%4,%5,%6,%7}, {%8,%9}, {%0,%1,%2,%3};" \
        : "+f"(c[0]), "+f"(c[1]), "+f"(c[2]), "+f"(c[3]) \
        : "r"(a0), "r"(a1), "r"(a2), "r"(a3), "r"(b0), "r"(b1))

// ---------------- W -> split-fp16 fragments (B-fragment order, m16n8k16) ----------------
__global__ void wfrag_k(const float* __restrict__ Ws) {
    int i = blockIdx.x * blockDim.x + threadIdx.x;
    if (i >= N_LAYERS * D * D) return;
    int l = i / (D * D);
    int rem = i - l * (D * D);
    int o = rem / D;           // Ws[l][o][k]
    int k = rem - o * D;
    float v = Ws[i];
    __half hi = __float2half_rn(v);
    __half lo = __float2half_rn(v - __half2float(hi));
    int kstep = k >> 4, kin = k & 15;
    int tig = (kin & 7) >> 1;
    int hpos = kin & 1;
    int b01 = kin >> 3;        // 0 -> b0, 1 -> b1
    int nt = o >> 3, gg = o & 7;
    int lane = gg * 4 + tig;
    size_t base = ((((size_t)l * KSTEPS + kstep) * 16 + nt) * 32 + lane) * 8;
    g_wfh[base + b01 * 2 + hpos]     = hi;
    g_wfh[base + 4 + b01 * 2 + hpos] = lo;
}

// ---------------- layer-0 input split ----------------
__global__ void conv0_k(const float* __restrict__ X) {
    int i = blockIdx.x * blockDim.x + threadIdx.x;
    if (i >= ND / 2) return;
    float2 v = ((const float2*)X)[i];
    __half hx = __float2half_rn(v.x), hy = __float2half_rn(v.y);
    __half lx = __float2half_rn(v.x - __half2float(hx));
    __half ly = __float2half_rn(v.y - __half2float(hy));
    ((__half2*)g_xh)[i] = __halves2half2(hx, hy);
    ((__half2*)g_xl)[i] = __halves2half2(lx, ly);
}

// ---------------- zero ----------------
__global__ void zero_misc_k() {
    int i = blockIdx.x * blockDim.x + threadIdx.x;
    if (i < N_NODES) { g_deg[i] = 0; g_cur[i] = 0; }
    if (i < N_GRAPHS) { g_gsum[i] = 0.f; g_gcnt[i] = 0; }
}

// ---------------- degree histogram ----------------
__global__ void deg_k(const int* __restrict__ ei) {
    int e = blockIdx.x * blockDim.x + threadIdx.x;
    if (e >= N_EDGES) return;
    atomicAdd(&g_deg[ei[N_EDGES + e]], 1);
}

// ---------------- scan (also computes dis) ----------------
__global__ void scan1_k() {
    __shared__ int sm[SCAN_BLK];
    int tid = threadIdx.x;
    int gid = blockIdx.x * SCAN_BLK + tid;
    int v = 0;
    if (gid < N_NODES) {
        v = g_deg[gid];
        g_dis[gid] = rsqrtf((float)(v + 1));
    }
    sm[tid] = v;
    __syncthreads();
    #pragma unroll
    for (int o = 1; o < SCAN_BLK; o <<= 1) {
        int t = (tid >= o) ? sm[tid - o] : 0;
        __syncthreads();
        sm[tid] += t;
        __syncthreads();
    }
    if (gid < N_NODES) g_off[gid] = sm[tid] - v;
    if (tid == SCAN_BLK - 1) g_bsum[blockIdx.x] = sm[tid];
}
__global__ void scan2_k() {
    if (threadIdx.x == 0) {
        int run = 0;
        for (int i = 0; i < SCAN_NBLK; i++) {
            int t = g_bsum[i];
            g_bsum[i] = run;
            run += t;
        }
    }
}
__global__ void scan3_k() {
    int gid = blockIdx.x * blockDim.x + threadIdx.x;
    if (gid < N_NODES) g_off[gid] += g_bsum[gid / SCAN_BLK];
    if (gid == 0) g_off[N_NODES] = N_EDGES;
}

// ---------------- counting-sort placement ----------------
__global__ void place_k(const int* __restrict__ ei) {
    int e = blockIdx.x * blockDim.x + threadIdx.x;
    if (e >= N_EDGES) return;
    int r = ei[e];
    int c = ei[N_EDGES + e];
    int idx = g_off[c] + atomicAdd(&g_cur[c], 1);
    g_em[idx] = make_float2(__int_as_float(r), g_dis[r] * g_dis[c]);
}

// ---------------- tensor-core GEMM: H = X @ W^T via split-fp16 (3 mma, k=16) ----------
// 256 threads (8 warps). Block tile = 128 rows x 64 cols (grid x2: bx = rowblk*2 + ch).
// Warp tile = 16 rows x 64 cols -> acc[8][4] = 32 regs -> >=2 CTAs/SM.
// A: direct LDG.32 from persistent fp16 hi/lo (padded rows). B: 1 LDG.128/(kstep,nt).
__global__ void __launch_bounds__(256, 2)
gemm_tc_k(const __half* __restrict__ XH, const __half* __restrict__ XL,
          const uint4* __restrict__ Fr, float* __restrict__ H) {
    int tid = threadIdx.x;
    int wid = tid >> 5;
    int lane = tid & 31;
    int g = lane >> 2, tig = lane & 3;
    int rowblk = blockIdx.x >> 1;
    int ch = blockIdx.x & 1;                    // col half: nt in [ch*8, ch*8+8)
    int r1 = rowblk * 128 + wid * 16 + g;       // rows for c0/c1 (a0/a2)
    int r2 = r1 + 8;                            // rows for c2/c3 (a1/a3)

    const __half* a0p = XH + (size_t)r1 * D + 2 * tig;
    const __half* a1p = XH + (size_t)r2 * D + 2 * tig;
    const __half* l0p = XL + (size_t)r1 * D + 2 * tig;
    const __half* l1p = XL + (size_t)r2 * D + 2 * tig;

    float acc[8][4];
    #pragma unroll
    for (int nt = 0; nt < 8; nt++) {
        acc[nt][0] = 0.f; acc[nt][1] = 0.f; acc[nt][2] = 0.f; acc[nt][3] = 0.f;
    }

    #pragma unroll
    for (int kstep = 0; kstep < KSTEPS; kstep++) {
        int k = kstep * 16;
        uint32_t ah0 = *(const uint32_t*)(a0p + k);
        uint32_t ah1 = *(const uint32_t*)(a1p + k);
        uint32_t ah2 = *(const uint32_t*)(a0p + k + 8);
        uint32_t ah3 = *(const uint32_t*)(a1p + k + 8);
        uint32_t al0 = *(const uint32_t*)(l0p + k);
        uint32_t al1 = *(const uint32_t*)(l1p + k);
        uint32_t al2 = *(const uint32_t*)(l0p + k + 8);
        uint32_t al3 = *(const uint32_t*)(l1p + k + 8);

        const uint4* bp = Fr + (kstep * 16 + ch * 8) * 32 + lane;

        #pragma unroll
        for (int nt = 0; nt < 8; nt++) {
            uint4 f = __ldg(bp + nt * 32);    // (bh0, bh1, bl0, bl1)
            MMA_F16(acc[nt], ah0, ah1, ah2, ah3, f.x, f.y);   // hi * hi
            MMA_F16(acc[nt], ah0, ah1, ah2, ah3, f.z, f.w);   // hi * lo
            MMA_F16(acc[nt], al0, al1, al2, al3, f.x, f.y);   // lo * hi
        }
    }

    // store (rows padded -> no guards)
    #pragma unroll
    for (int nt = 0; nt < 8; nt++) {
        int col = ch * 64 + nt * 8 + tig * 2;
        *(float2*)(H + (size_t)r1 * D + col) = make_float2(acc[nt][0], acc[nt][1]);
        *(float2*)(H + (size_t)r2 * D + col) = make_float2(acc[nt][2], acc[nt][3]);
    }
}

// ---------------- fused gather + self-loop + bias + relu; emits fp16 hi/lo ----------
__global__ void gather_k(const float* __restrict__ bias, int write_f32) {
    int gt = blockIdx.x * blockDim.x + threadIdx.x;
    int c = gt >> 5;
    int lane = gt & 31;
    if (c >= N_NODES) return;

    int s = g_off[c];
    int e = g_off[c + 1];
    float4 acc = make_float4(0.f, 0.f, 0.f, 0.f);

    int i = s;
    for (; i + 4 <= e; i += 4) {
        float2 m0 = g_em[i + 0];
        float2 m1 = g_em[i + 1];
        float2 m2 = g_em[i + 2];
        float2 m3 = g_em[i + 3];
        const float4 v0 = *(const float4*)(g_h + (size_t)__float_as_int(m0.x) * D + lane * 4);
        const float4 v1 = *(const float4*)(g_h + (size_t)__float_as_int(m1.x) * D + lane * 4);
        const float4 v2 = *(const float4*)(g_h + (size_t)__float_as_int(m2.x) * D + lane * 4);
        const float4 v3 = *(const float4*)(g_h + (size_t)__float_as_int(m3.x) * D + lane * 4);
        acc.x += m0.y * v0.x + m1.y * v1.x + m2.y * v2.x + m3.y * v3.x;
        acc.y += m0.y * v0.y + m1.y * v1.y + m2.y * v2.y + m3.y * v3.y;
        acc.z += m0.y * v0.z + m1.y * v1.z + m2.y * v2.z + m3.y * v3.z;
        acc.w += m0.y * v0.w + m1.y * v1.w + m2.y * v2.w + m3.y * v3.w;
    }
    for (; i < e; i++) {
        float2 m = g_em[i];
        const float4 v = *(const float4*)(g_h + (size_t)__float_as_int(m.x) * D + lane * 4);
        acc.x += m.y * v.x; acc.y += m.y * v.y; acc.z += m.y * v.z; acc.w += m.y * v.w;
    }

    float d = g_dis[c];
    float d2 = d * d;
    float4 h = *(const float4*)(g_h + (size_t)c * D + lane * 4);
    float4 b = ((const float4*)bias)[lane];
    float4 o;
    o.x = fmaxf(acc.x + d2 * h.x + b.x, 0.f);
    o.y = fmaxf(acc.y + d2 * h.y + b.y, 0.f);
    o.z = fmaxf(acc.z + d2 * h.z + b.z, 0.f);
    o.w = fmaxf(acc.w + d2 * h.w + b.w, 0.f);

    size_t base = (size_t)c * D + lane * 4;
    __half h0 = __float2half_rn(o.x), h1 = __float2half_rn(o.y);
    __half h2 = __float2half_rn(o.z), h3 = __float2half_rn(o.w);
    *(__half2*)(g_xh + base)     = __halves2half2(h0, h1);
    *(__half2*)(g_xh + base + 2) = __halves2half2(h2, h3);
    __half l0 = __float2half_rn(o.x - __half2float(h0));
    __half l1 = __float2half_rn(o.y - __half2float(h1));
    __half l2 = __float2half_rn(o.z - __half2float(h2));
    __half l3 = __float2half_rn(o.w - __half2float(h3));
    *(__half2*)(g_xl + base)     = __halves2half2(l0, l1);
    *(__half2*)(g_xl + base + 2) = __halves2half2(l2, l3);
    if (write_f32) *(float4*)(g_x + base) = o;
}

// ---------------- pooling ----------------
__global__ void pool_k(const int* __restrict__ batch, const float* __restrict__ lw) {
    int gt = blockIdx.x * blockDim.x + threadIdx.x;
    int node = gt >> 5;
    int lane = gt & 31;
    if (node >= N_NODES) return;
    float4 xv = ((const float4*)g_x)[node * 32 + lane];
    float4 wv = ((const float4*)lw)[lane];
    float s = xv.x * wv.x + xv.y * wv.y + xv.z * wv.z + xv.w * wv.w;
    #pragma unroll
    for (int o = 16; o > 0; o >>= 1) s += __shfl_xor_sync(0xFFFFFFFFu, s, o);
    if (lane == 0) {
        int g = batch[node];
        atomicAdd(&g_gsum[g], s);
        atomicAdd(&g_gcnt[g], 1);
    }
}

__global__ void final_k(const float* __restrict__ lb, float* __restrict__ out) {
    int g = blockIdx.x * blockDim.x + threadIdx.x;
    if (g >= N_GRAPHS) return;
    float c = fmaxf((float)g_gcnt[g], 1.0f);
    out[g] = g_gsum[g] / c + lb[0];
}

// ---------------- launcher ----------------
extern "C" void kernel_launch(void* const* d_in, const int* in_sizes, int n_in,
                              void* d_out, int out_size) {
    const float* x    = (const float*)d_in[0];
    const int*   ei   = (const int*)d_in[1];    // int32 (JAX x64 disabled)
    const int*   bat  = (const int*)d_in[2];
    const float* Ws   = (const float*)d_in[3];
    const float* bs   = (const float*)d_in[4];
    const float* lw   = (const float*)d_in[5];
    const float* lb   = (const float*)d_in[6];
    float*       out  = (float*)d_out;

    float *h_p;
    __half *xh_p, *xl_p, *wfh_p;
    cudaGetSymbolAddress((void**)&h_p,   g_h);
    cudaGetSymbolAddress((void**)&xh_p,  g_xh);
    cudaGetSymbolAddress((void**)&xl_p,  g_xl);
    cudaGetSymbolAddress((void**)&wfh_p, g_wfh);

    const int gemm_blocks = (NROWS / 128) * 2;       // 782 (row blocks x col halves)
    const int gather_blocks = (N_NODES * 32 + 255) / 256;

    // launches 1-3: gemm prerequisites (keeps gemm as launch #4 for ncu)
    wfrag_k<<<(N_LAYERS * D * D + 255) / 256, 256>>>(Ws);
    conv0_k<<<(ND / 2 + 255) / 256, 256>>>(x);
    zero_misc_k<<<(N_NODES + 255) / 256, 256>>>();

    // launch 4: layer-0 GEMM (ncu capture target)
    gemm_tc_k<<<gemm_blocks, 256>>>(
        xh_p, xl_p, (const uint4*)wfh_p, h_p);

    // edge preprocessing (independent of gemm0)
    deg_k<<<(N_EDGES + 255) / 256, 256>>>(ei);
    scan1_k<<<SCAN_NBLK, SCAN_BLK>>>();
    scan2_k<<<1, 32>>>();
    scan3_k<<<(N_NODES + 255) / 256, 256>>>();
    place_k<<<(N_EDGES + 255) / 256, 256>>>(ei);

    // layer 0 gather, then layers 1..2
    gather_k<<<gather_blocks, 256>>>(bs, 0);
    for (int l = 1; l < N_LAYERS; l++) {
        gemm_tc_k<<<gemm_blocks, 256>>>(
            xh_p, xl_p, (const uint4*)(wfh_p + (size_t)l * FRAGH_PER_LAYER), h_p);
        gather_k<<<gather_blocks, 256>>>(bs + l * D, (l == N_LAYERS - 1) ? 1 : 0);
    }

    // pooling + output
    pool_k<<<(N_NODES * 32 + 255) / 256, 256>>>(bat, lw);
    final_k<<<(N_GRAPHS + 255) / 256, 256>>>(lb, out);
}

// round 14
// speedup vs baseline: 1.0988x; 1.0988x over previous
#include <cuda_runtime.h>
#include <cuda_fp16.h>
#include <cstdint>

#define N_NODES 50000
#define N_EDGES 800000
#define D 128
#define N_LAYERS 3
#define N_GRAPHS 512
#define NROWS 50176                     // padded to 196*256 (device globals zero-init)
#define ND (N_NODES * D)
#define NDP (NROWS * D)

#define SCAN_BLK 512
#define SCAN_NBLK ((N_NODES + SCAN_BLK - 1) / SCAN_BLK)   // 98

// fp16 fragments: 8 ksteps x 16 nt x 32 lanes x 8 halves (bh0,bh1,bl0,bl1 as half2s)
#define KSTEPS (D / 16)                       // 8
#define FRAGH_PER_LAYER (KSTEPS * 16 * 32 * 8)   // 32768 halves = 64KB

// ---------------- scratch (device globals; no allocation allowed) ----------------
__device__ float  g_h[NDP];                 // post-GEMM features (fp32), padded
__device__ __half g_xh[NDP];                // layer input, fp16 hi, padded
__device__ __half g_xl[NDP];                // layer input, fp16 lo (residual), padded
__device__ float  g_x[ND];                  // final layer output (pool input)
__device__ __half g_wfh[N_LAYERS * FRAGH_PER_LAYER];  // W split-fp16 fragments
__device__ float  g_dis[N_NODES];
__device__ int    g_deg[N_NODES];
__device__ int    g_cur[N_NODES];
__device__ int    g_off[N_NODES + 1];
__device__ int    g_bsum[SCAN_NBLK];
__device__ float2 g_em[N_EDGES];            // (src as int bits, norm)
__device__ float  g_gsum[N_GRAPHS];
__device__ int    g_gcnt[N_GRAPHS];

#define MMA_F16(c, a0, a1, a2, a3, b0, b1) \
    asm volatile("mma.sync.aligned.m16n8k16.row.col.f32.f16.f16.f32 " \
        "{%0,%1,%2,%3}, {%4,%5,%6,%7}, {%8,%9}, {%0,%1,%2,%3};" \
        : "+f"(c[0]), "+f"(c[1]), "+f"(c[2]), "+f"(c[3]) \
        : "r"(a0), "r"(a1), "r"(a2), "r"(a3), "r"(b0), "r"(b1))

// ---------------- W -> split-fp16 fragments (B-fragment order, m16n8k16) ----------------
__global__ void wfrag_k(const float* __restrict__ Ws) {
    int i = blockIdx.x * blockDim.x + threadIdx.x;
    if (i >= N_LAYERS * D * D) return;
    int l = i / (D * D);
    int rem = i - l * (D * D);
    int o = rem / D;           // Ws[l][o][k]
    int k = rem - o * D;
    float v = Ws[i];
    __half hi = __float2half_rn(v);
    __half lo = __float2half_rn(v - __half2float(hi));
    int kstep = k >> 4, kin = k & 15;
    int tig = (kin & 7) >> 1;
    int hpos = kin & 1;
    int b01 = kin >> 3;        // 0 -> b0, 1 -> b1
    int nt = o >> 3, gg = o & 7;
    int lane = gg * 4 + tig;
    size_t base = ((((size_t)l * KSTEPS + kstep) * 16 + nt) * 32 + lane) * 8;
    g_wfh[base + b01 * 2 + hpos]     = hi;
    g_wfh[base + 4 + b01 * 2 + hpos] = lo;
}

// ---------------- layer-0 input split ----------------
__global__ void conv0_k(const float* __restrict__ X) {
    int i = blockIdx.x * blockDim.x + threadIdx.x;
    if (i >= ND / 2) return;
    float2 v = ((const float2*)X)[i];
    __half hx = __float2half_rn(v.x), hy = __float2half_rn(v.y);
    __half lx = __float2half_rn(v.x - __half2float(hx));
    __half ly = __float2half_rn(v.y - __half2float(hy));
    ((__half2*)g_xh)[i] = __halves2half2(hx, hy);
    ((__half2*)g_xl)[i] = __halves2half2(lx, ly);
}

// ---------------- zero ----------------
__global__ void zero_misc_k() {
    int i = blockIdx.x * blockDim.x + threadIdx.x;
    if (i < N_NODES) { g_deg[i] = 0; g_cur[i] = 0; }
    if (i < N_GRAPHS) { g_gsum[i] = 0.f; g_gcnt[i] = 0; }
}

// ---------------- degree histogram ----------------
__global__ void deg_k(const int* __restrict__ ei) {
    int e = blockIdx.x * blockDim.x + threadIdx.x;
    if (e >= N_EDGES) return;
    atomicAdd(&g_deg[ei[N_EDGES + e]], 1);
}

// ---------------- scan (also computes dis) ----------------
__global__ void scan1_k() {
    __shared__ int sm[SCAN_BLK];
    int tid = threadIdx.x;
    int gid = blockIdx.x * SCAN_BLK + tid;
    int v = 0;
    if (gid < N_NODES) {
        v = g_deg[gid];
        g_dis[gid] = rsqrtf((float)(v + 1));
    }
    sm[tid] = v;
    __syncthreads();
    #pragma unroll
    for (int o = 1; o < SCAN_BLK; o <<= 1) {
        int t = (tid >= o) ? sm[tid - o] : 0;
        __syncthreads();
        sm[tid] += t;
        __syncthreads();
    }
    if (gid < N_NODES) g_off[gid] = sm[tid] - v;
    if (tid == SCAN_BLK - 1) g_bsum[blockIdx.x] = sm[tid];
}
__global__ void scan2_k() {
    if (threadIdx.x == 0) {
        int run = 0;
        for (int i = 0; i < SCAN_NBLK; i++) {
            int t = g_bsum[i];
            g_bsum[i] = run;
            run += t;
        }
    }
}
__global__ void scan3_k() {
    int gid = blockIdx.x * blockDim.x + threadIdx.x;
    if (gid < N_NODES) g_off[gid] += g_bsum[gid / SCAN_BLK];
    if (gid == 0) g_off[N_NODES] = N_EDGES;
}

// ---------------- counting-sort placement ----------------
__global__ void place_k(const int* __restrict__ ei) {
    int e = blockIdx.x * blockDim.x + threadIdx.x;
    if (e >= N_EDGES) return;
    int r = ei[e];
    int c = ei[N_EDGES + e];
    int idx = g_off[c] + atomicAdd(&g_cur[c], 1);
    g_em[idx] = make_float2(__int_as_float(r), g_dis[r] * g_dis[c]);
}

// ---------------- tensor-core GEMM: H = X @ W^T via split-fp16 (3 mma, k=16) ----------
// 256 threads (8 warps). Block tile = 256 rows x 64 cols (bx = rowblk*2 + ch).
// Warp tile = 32 rows x 64 cols (TWO m16 row-sets) -> each B uint4 feeds 6 MMAs.
// acc[2][8][4]=64 regs, ~110 total -> 2 CTAs/SM. A: LDG.32 direct; B: L1-resident.
__global__ void __launch_bounds__(256, 2)
gemm_tc_k(const __half* __restrict__ XH, const __half* __restrict__ XL,
          const uint4* __restrict__ Fr, float* __restrict__ H) {
    int tid = threadIdx.x;
    int wid = tid >> 5;
    int lane = tid & 31;
    int g = lane >> 2, tig = lane & 3;
    int rowblk = blockIdx.x >> 1;
    int ch = blockIdx.x & 1;                    // col half: nt in [ch*8, ch*8+8)
    int rA = rowblk * 256 + wid * 32 + g;       // row-set 0: rows rA, rA+8
    int rB = rA + 16;                           // row-set 1: rows rB, rB+8

    const __half* a0p = XH + (size_t)rA * D + 2 * tig;
    const __half* a1p = XH + (size_t)(rA + 8) * D + 2 * tig;
    const __half* l0p = XL + (size_t)rA * D + 2 * tig;
    const __half* l1p = XL + (size_t)(rA + 8) * D + 2 * tig;
    const __half* a2p = XH + (size_t)rB * D + 2 * tig;
    const __half* a3p = XH + (size_t)(rB + 8) * D + 2 * tig;
    const __half* l2p = XL + (size_t)rB * D + 2 * tig;
    const __half* l3p = XL + (size_t)(rB + 8) * D + 2 * tig;

    float acc[2][8][4];
    #pragma unroll
    for (int rs = 0; rs < 2; rs++)
        #pragma unroll
        for (int nt = 0; nt < 8; nt++) {
            acc[rs][nt][0] = 0.f; acc[rs][nt][1] = 0.f;
            acc[rs][nt][2] = 0.f; acc[rs][nt][3] = 0.f;
        }

    #pragma unroll
    for (int kstep = 0; kstep < KSTEPS; kstep++) {
        int k = kstep * 16;
        // row-set 0 fragments
        uint32_t xh0 = *(const uint32_t*)(a0p + k);
        uint32_t xh1 = *(const uint32_t*)(a1p + k);
        uint32_t xh2 = *(const uint32_t*)(a0p + k + 8);
        uint32_t xh3 = *(const uint32_t*)(a1p + k + 8);
        uint32_t xl0 = *(const uint32_t*)(l0p + k);
        uint32_t xl1 = *(const uint32_t*)(l1p + k);
        uint32_t xl2 = *(const uint32_t*)(l0p + k + 8);
        uint32_t xl3 = *(const uint32_t*)(l1p + k + 8);
        // row-set 1 fragments
        uint32_t yh0 = *(const uint32_t*)(a2p + k);
        uint32_t yh1 = *(const uint32_t*)(a3p + k);
        uint32_t yh2 = *(const uint32_t*)(a2p + k + 8);
        uint32_t yh3 = *(const uint32_t*)(a3p + k + 8);
        uint32_t yl0 = *(const uint32_t*)(l2p + k);
        uint32_t yl1 = *(const uint32_t*)(l3p + k);
        uint32_t yl2 = *(const uint32_t*)(l2p + k + 8);
        uint32_t yl3 = *(const uint32_t*)(l3p + k + 8);

        const uint4* bp = Fr + (kstep * 16 + ch * 8) * 32 + lane;

        #pragma unroll
        for (int nt = 0; nt < 8; nt++) {
            uint4 f = __ldg(bp + nt * 32);    // (bh0, bh1, bl0, bl1)
            MMA_F16(acc[0][nt], xh0, xh1, xh2, xh3, f.x, f.y);   // hi*hi rs0
            MMA_F16(acc[0][nt], xh0, xh1, xh2, xh3, f.z, f.w);   // hi*lo rs0
            MMA_F16(acc[0][nt], xl0, xl1, xl2, xl3, f.x, f.y);   // lo*hi rs0
            MMA_F16(acc[1][nt], yh0, yh1, yh2, yh3, f.x, f.y);   // hi*hi rs1
            MMA_F16(acc[1][nt], yh0, yh1, yh2, yh3, f.z, f.w);   // hi*lo rs1
            MMA_F16(acc[1][nt], yl0, yl1, yl2, yl3, f.x, f.y);   // lo*hi rs1
        }
    }

    // store (rows padded -> no guards)
    #pragma unroll
    for (int rs = 0; rs < 2; rs++) {
        int r1 = (rs == 0) ? rA : rB;
        #pragma unroll
        for (int nt = 0; nt < 8; nt++) {
            int col = ch * 64 + nt * 8 + tig * 2;
            *(float2*)(H + (size_t)r1 * D + col) =
                make_float2(acc[rs][nt][0], acc[rs][nt][1]);
            *(float2*)(H + (size_t)(r1 + 8) * D + col) =
                make_float2(acc[rs][nt][2], acc[rs][nt][3]);
        }
    }
}

// ---------------- fused gather + self-loop + bias + relu; emits fp16 hi/lo ----------
__global__ void gather_k(const float* __restrict__ bias, int write_f32) {
    int gt = blockIdx.x * blockDim.x + threadIdx.x;
    int c = gt >> 5;
    int lane = gt & 31;
    if (c >= N_NODES) return;

    int s = g_off[c];
    int e = g_off[c + 1];
    float4 acc = make_float4(0.f, 0.f, 0.f, 0.f);

    int i = s;
    for (; i + 4 <= e; i += 4) {
        float2 m0 = g_em[i + 0];
        float2 m1 = g_em[i + 1];
        float2 m2 = g_em[i + 2];
        float2 m3 = g_em[i + 3];
        const float4 v0 = *(const float4*)(g_h + (size_t)__float_as_int(m0.x) * D + lane * 4);
        const float4 v1 = *(const float4*)(g_h + (size_t)__float_as_int(m1.x) * D + lane * 4);
        const float4 v2 = *(const float4*)(g_h + (size_t)__float_as_int(m2.x) * D + lane * 4);
        const float4 v3 = *(const float4*)(g_h + (size_t)__float_as_int(m3.x) * D + lane * 4);
        acc.x += m0.y * v0.x + m1.y * v1.x + m2.y * v2.x + m3.y * v3.x;
        acc.y += m0.y * v0.y + m1.y * v1.y + m2.y * v2.y + m3.y * v3.y;
        acc.z += m0.y * v0.z + m1.y * v1.z + m2.y * v2.z + m3.y * v3.z;
        acc.w += m0.y * v0.w + m1.y * v1.w + m2.y * v2.w + m3.y * v3.w;
    }
    for (; i < e; i++) {
        float2 m = g_em[i];
        const float4 v = *(const float4*)(g_h + (size_t)__float_as_int(m.x) * D + lane * 4);
        acc.x += m.y * v.x; acc.y += m.y * v.y; acc.z += m.y * v.z; acc.w += m.y * v.w;
    }

    float d = g_dis[c];
    float d2 = d * d;
    float4 h = *(const float4*)(g_h + (size_t)c * D + lane * 4);
    float4 b = ((const float4*)bias)[lane];
    float4 o;
    o.x = fmaxf(acc.x + d2 * h.x + b.x, 0.f);
    o.y = fmaxf(acc.y + d2 * h.y + b.y, 0.f);
    o.z = fmaxf(acc.z + d2 * h.z + b.z, 0.f);
    o.w = fmaxf(acc.w + d2 * h.w + b.w, 0.f);

    size_t base = (size_t)c * D + lane * 4;
    __half h0 = __float2half_rn(o.x), h1 = __float2half_rn(o.y);
    __half h2 = __float2half_rn(o.z), h3 = __float2half_rn(o.w);
    *(__half2*)(g_xh + base)     = __halves2half2(h0, h1);
    *(__half2*)(g_xh + base + 2) = __halves2half2(h2, h3);
    __half l0 = __float2half_rn(o.x - __half2float(h0));
    __half l1 = __float2half_rn(o.y - __half2float(h1));
    __half l2 = __float2half_rn(o.z - __half2float(h2));
    __half l3 = __float2half_rn(o.w - __half2float(h3));
    *(__half2*)(g_xl + base)     = __halves2half2(l0, l1);
    *(__half2*)(g_xl + base + 2) = __halves2half2(l2, l3);
    if (write_f32) *(float4*)(g_x + base) = o;
}

// ---------------- pooling ----------------
__global__ void pool_k(const int* __restrict__ batch, const float* __restrict__ lw) {
    int gt = blockIdx.x * blockDim.x + threadIdx.x;
    int node = gt >> 5;
    int lane = gt & 31;
    if (node >= N_NODES) return;
    float4 xv = ((const float4*)g_x)[node * 32 + lane];
    float4 wv = ((const float4*)lw)[lane];
    float s = xv.x * wv.x + xv.y * wv.y + xv.z * wv.z + xv.w * wv.w;
    #pragma unroll
    for (int o = 16; o > 0; o >>= 1) s += __shfl_xor_sync(0xFFFFFFFFu, s, o);
    if (lane == 0) {
        int g = batch[node];
        atomicAdd(&g_gsum[g], s);
        atomicAdd(&g_gcnt[g], 1);
    }
}

__global__ void final_k(const float* __restrict__ lb, float* __restrict__ out) {
    int g = blockIdx.x * blockDim.x + threadIdx.x;
    if (g >= N_GRAPHS) return;
    float c = fmaxf((float)g_gcnt[g], 1.0f);
    out[g] = g_gsum[g] / c + lb[0];
}

// ---------------- launcher ----------------
extern "C" void kernel_launch(void* const* d_in, const int* in_sizes, int n_in,
                              void* d_out, int out_size) {
    const float* x    = (const float*)d_in[0];
    const int*   ei   = (const int*)d_in[1];    // int32 (JAX x64 disabled)
    const int*   bat  = (const int*)d_in[2];
    const float* Ws   = (const float*)d_in[3];
    const float* bs   = (const float*)d_in[4];
    const float* lw   = (const float*)d_in[5];
    const float* lb   = (const float*)d_in[6];
    float*       out  = (float*)d_out;

    float *h_p;
    __half *xh_p, *xl_p, *wfh_p;
    cudaGetSymbolAddress((void**)&h_p,   g_h);
    cudaGetSymbolAddress((void**)&xh_p,  g_xh);
    cudaGetSymbolAddress((void**)&xl_p,  g_xl);
    cudaGetSymbolAddress((void**)&wfh_p, g_wfh);

    const int gemm_blocks = (NROWS / 256) * 2;       // 392 (row blocks x col halves)
    const int gather_blocks = (N_NODES * 32 + 255) / 256;

    // launches 1-3: gemm prerequisites (keeps gemm as launch #4 for ncu)
    wfrag_k<<<(N_LAYERS * D * D + 255) / 256, 256>>>(Ws);
    conv0_k<<<(ND / 2 + 255) / 256, 256>>>(x);
    zero_misc_k<<<(N_NODES + 255) / 256, 256>>>();

    // launch 4: layer-0 GEMM (ncu capture target)
    gemm_tc_k<<<gemm_blocks, 256>>>(
        xh_p, xl_p, (const uint4*)wfh_p, h_p);

    // edge preprocessing (independent of gemm0)
    deg_k<<<(N_EDGES + 255) / 256, 256>>>(ei);
    scan1_k<<<SCAN_NBLK, SCAN_BLK>>>();
    scan2_k<<<1, 32>>>();
    scan3_k<<<(N_NODES + 255) / 256, 256>>>();
    place_k<<<(N_EDGES + 255) / 256, 256>>>(ei);

    // layer 0 gather, then layers 1..2
    gather_k<<<gather_blocks, 256>>>(bs, 0);
    for (int l = 1; l < N_LAYERS; l++) {
        gemm_tc_k<<<gemm_blocks, 256>>>(
            xh_p, xl_p, (const uint4*)(wfh_p + (size_t)l * FRAGH_PER_LAYER), h_p);
        gather_k<<<gather_blocks, 256>>>(bs + l * D, (l == N_LAYERS - 1) ? 1 : 0);
    }

    // pooling + output
    pool_k<<<(N_NODES * 32 + 255) / 256, 256>>>(bat, lw);
    final_k<<<(N_GRAPHS + 255) / 256, 256>>>(lb, out);
}